// round 1
// baseline (speedup 1.0000x reference)
#include <cuda_runtime.h>
#include <math.h>

// Problem constants
constexpr int T_SEQ  = 2048;
constexpr int NB     = 2;
constexpr int NH     = 4;
constexpr int DK     = 256;
constexpr int DV     = 512;
constexpr int DMODEL = 1024;
constexpr int KDIM   = NH * DK;    // 1024
constexpr int VDIM   = NH * DV;    // 2048
constexpr int MROWS  = NB * T_SEQ; // 4096

// Scratch (device globals; no allocations allowed)
__device__ __align__(128) float g_q[MROWS * KDIM];
__device__ __align__(128) float g_k[MROWS * KDIM];
__device__ __align__(128) float g_v[MROWS * VDIM];
__device__ __align__(128) float g_g[MROWS * VDIM];
__device__ __align__(128) float g_o[MROWS * VDIM];

__device__ __forceinline__ float* scratch_ptr(int sel) {
    switch (sel) {
        case 0: return g_q;
        case 1: return g_k;
        case 2: return g_v;
        case 3: return g_g;
        case 4: return g_o;
    }
    return nullptr;
}

// ---------------------------------------------------------------------------
// SGEMM: C[M,N] = A[M,K] @ B[N,K]^T   (both row-major, K contiguous)
// 128x128 tile, BK=16, 256 threads, 8x8 micro-tile.
// asel/csel >= 0 selects internal scratch for A/C.
// ---------------------------------------------------------------------------
__global__ __launch_bounds__(256) void sgemm_nt(
    const float* __restrict__ Aext, int asel,
    const float* __restrict__ W,
    float* __restrict__ Cext, int csel,
    int M, int N, int K)
{
    const float* A = (asel >= 0) ? scratch_ptr(asel) : Aext;
    float* C       = (csel >= 0) ? scratch_ptr(csel) : Cext;

    __shared__ __align__(16) float As[16][132];
    __shared__ __align__(16) float Bs[16][132];

    const int bm = blockIdx.y * 128;
    const int bn = blockIdx.x * 128;
    const int tid = threadIdx.x;
    const int tr = tid >> 4;   // 0..15
    const int tc = tid & 15;   // 0..15

    float acc[8][8];
#pragma unroll
    for (int i = 0; i < 8; i++)
#pragma unroll
        for (int j = 0; j < 8; j++) acc[i][j] = 0.0f;

    for (int k0 = 0; k0 < K; k0 += 16) {
#pragma unroll
        for (int i = 0; i < 2; i++) {
            int idx = i * 256 + tid;         // 0..511
            int row = idx >> 2;              // 0..127
            int kq  = (idx & 3) * 4;         // 0,4,8,12
            float4 a = *(const float4*)(A + (size_t)(bm + row) * K + k0 + kq);
            As[kq + 0][row] = a.x; As[kq + 1][row] = a.y;
            As[kq + 2][row] = a.z; As[kq + 3][row] = a.w;
            float4 b = *(const float4*)(W + (size_t)(bn + row) * K + k0 + kq);
            Bs[kq + 0][row] = b.x; Bs[kq + 1][row] = b.y;
            Bs[kq + 2][row] = b.z; Bs[kq + 3][row] = b.w;
        }
        __syncthreads();
#pragma unroll
        for (int kk = 0; kk < 16; kk++) {
            float ra[8], rb[8];
            *(float4*)(ra)     = *(const float4*)&As[kk][tr * 8];
            *(float4*)(ra + 4) = *(const float4*)&As[kk][tr * 8 + 4];
            *(float4*)(rb)     = *(const float4*)&Bs[kk][tc * 8];
            *(float4*)(rb + 4) = *(const float4*)&Bs[kk][tc * 8 + 4];
#pragma unroll
            for (int i = 0; i < 8; i++)
#pragma unroll
                for (int j = 0; j < 8; j++)
                    acc[i][j] += ra[i] * rb[j];
        }
        __syncthreads();
    }

#pragma unroll
    for (int i = 0; i < 8; i++) {
        float* crow = C + (size_t)(bm + tr * 8 + i) * N + bn + tc * 8;
        *(float4*)(crow)     = make_float4(acc[i][0], acc[i][1], acc[i][2], acc[i][3]);
        *(float4*)(crow + 4) = make_float4(acc[i][4], acc[i][5], acc[i][6], acc[i][7]);
    }
}

// ---------------------------------------------------------------------------
// RoPE (in place on g_q, g_k) + q scale by dk^-0.5.
// Mirrors the reference's float32 computation path.
// ---------------------------------------------------------------------------
__global__ __launch_bounds__(256) void rope_kernel()
{
    int idx = blockIdx.x * 256 + threadIdx.x;      // 0 .. 2M-1
    int i  = idx & 127;                            // half index
    int h  = (idx >> 7) & 3;
    int bt = idx >> 9;                             // 0..4095
    int t  = bt & (T_SEQ - 1);
    size_t base = (size_t)bt * KDIM + h * DK;

    float e    = (float)(2 * i) * (1.0f / 256.0f);
    float invf = 1.0f / powf(10000.0f, e);
    float ang  = (float)t * invf;
    float sn, cs;
    sincosf(ang, &sn, &cs);

    float q1 = g_q[base + i], q2 = g_q[base + 128 + i];
    g_q[base + i]       = (q1 * cs - q2 * sn) * 0.0625f;
    g_q[base + 128 + i] = (q1 * sn + q2 * cs) * 0.0625f;
    float k1 = g_k[base + i], k2 = g_k[base + 128 + i];
    g_k[base + i]       = k1 * cs - k2 * sn;
    g_k[base + 128 + i] = k1 * sn + k2 * cs;
}

// ---------------------------------------------------------------------------
// Retention attention: o[b,h,t,:] = sum_{s<=t} exp(lam_h*(t-s)) (q_t.k_s) v_s
// Block: BM=32 queries for one (b,h). 256 threads. O accum in registers.
// ---------------------------------------------------------------------------
constexpr int BM = 32;
constexpr int BN = 64;

__global__ __launch_bounds__(256) void retention_attn()
{
    __shared__ __align__(16) float pool[8192];            // 32 KB, phase-shared
    __shared__ __align__(16) float Ss[BM][BN + 4];        // pitch 68

    float* Qs = pool;                   // [32][68] phase 1
    float* Ks = pool + 32 * 68;         // [64][68] phase 1
    float* Vs = pool;                   // [64][128] phase 2

    const int tid = threadIdx.x;
    const int bh = blockIdx.y;
    const int b = bh >> 2, h = bh & 3;
    const int t0 = blockIdx.x * BM;

    const float* Qb = g_q + (size_t)(b * T_SEQ) * KDIM + h * DK;
    const float* Kb = g_k + (size_t)(b * T_SEQ) * KDIM + h * DK;
    const float* Vb = g_v + (size_t)(b * T_SEQ) * VDIM + h * DV;

    const float lam = logf(1.0f - exp2f(-5.0f - (float)h));

    const int strow = tid >> 4;   // 0..15 (S rows: 2 each)
    const int stcol = tid & 15;   // 0..15 (S cols: 4 each)
    const int otr   = tid >> 5;   // 0..7  (O rows: 4 each)
    const int occ   = tid & 31;   // 0..31 (O cols: 4 per v-chunk)

    float acc[4][16];
#pragma unroll
    for (int i = 0; i < 4; i++)
#pragma unroll
        for (int j = 0; j < 16; j++) acc[i][j] = 0.0f;

    for (int s0 = 0; s0 < t0 + BM; s0 += BN) {
        float sacc[2][4] = {{0.f, 0.f, 0.f, 0.f}, {0.f, 0.f, 0.f, 0.f}};

        // ---- S = Q @ K^T over dk, streamed in 64-wide chunks ----
        for (int kc = 0; kc < DK; kc += 64) {
#pragma unroll
            for (int i = 0; i < 2; i++) {                 // Q tile 32x64
                int idx = i * 256 + tid;
                int row = idx >> 4;
                int ks  = (idx & 15) * 4;
                *(float4*)&Qs[row * 68 + ks] =
                    *(const float4*)(Qb + (size_t)(t0 + row) * KDIM + kc + ks);
            }
#pragma unroll
            for (int i = 0; i < 4; i++) {                 // K tile 64x64
                int idx = i * 256 + tid;
                int row = idx >> 4;
                int ks  = (idx & 15) * 4;
                *(float4*)&Ks[row * 68 + ks] =
                    *(const float4*)(Kb + (size_t)(s0 + row) * KDIM + kc + ks);
            }
            __syncthreads();
#pragma unroll
            for (int k4 = 0; k4 < 64; k4 += 4) {
                float4 qa = *(const float4*)&Qs[(2 * strow) * 68 + k4];
                float4 qb = *(const float4*)&Qs[(2 * strow + 1) * 68 + k4];
#pragma unroll
                for (int jc = 0; jc < 4; jc++) {
                    float4 kv = *(const float4*)&Ks[(4 * stcol + jc) * 68 + k4];
                    sacc[0][jc] += qa.x * kv.x + qa.y * kv.y + qa.z * kv.z + qa.w * kv.w;
                    sacc[1][jc] += qb.x * kv.x + qb.y * kv.y + qb.z * kv.z + qb.w * kv.w;
                }
            }
            __syncthreads();
        }

        // ---- decay + causal mask, store S ----
#pragma unroll
        for (int ii = 0; ii < 2; ii++) {
            int t = t0 + 2 * strow + ii;
#pragma unroll
            for (int jc = 0; jc < 4; jc++) {
                int s = s0 + 4 * stcol + jc;
                float w = (t >= s) ? expf(lam * (float)(t - s)) : 0.0f;
                Ss[2 * strow + ii][4 * stcol + jc] = sacc[ii][jc] * w;
            }
        }
        __syncthreads();

        // ---- O += S @ V, V streamed in 128-col chunks ----
#pragma unroll
        for (int vc = 0; vc < DV; vc += 128) {
#pragma unroll
            for (int i = 0; i < 8; i++) {
                int idx = i * 256 + tid;
                int row = idx >> 5;
                int cs  = (idx & 31) * 4;
                *(float4*)&Vs[row * 128 + cs] =
                    *(const float4*)(Vb + (size_t)(s0 + row) * VDIM + vc + cs);
            }
            __syncthreads();
            const int vq = vc >> 5;  // 0,4,8,12
#pragma unroll 16
            for (int s = 0; s < BN; s++) {
                float4 vv = *(const float4*)&Vs[s * 128 + occ * 4];
                float r0 = Ss[otr * 4 + 0][s];
                float r1 = Ss[otr * 4 + 1][s];
                float r2 = Ss[otr * 4 + 2][s];
                float r3 = Ss[otr * 4 + 3][s];
                acc[0][vq + 0] += r0 * vv.x; acc[0][vq + 1] += r0 * vv.y;
                acc[0][vq + 2] += r0 * vv.z; acc[0][vq + 3] += r0 * vv.w;
                acc[1][vq + 0] += r1 * vv.x; acc[1][vq + 1] += r1 * vv.y;
                acc[1][vq + 2] += r1 * vv.z; acc[1][vq + 3] += r1 * vv.w;
                acc[2][vq + 0] += r2 * vv.x; acc[2][vq + 1] += r2 * vv.y;
                acc[2][vq + 2] += r2 * vv.z; acc[2][vq + 3] += r2 * vv.w;
                acc[3][vq + 0] += r3 * vv.x; acc[3][vq + 1] += r3 * vv.y;
                acc[3][vq + 2] += r3 * vv.z; acc[3][vq + 3] += r3 * vv.w;
            }
            __syncthreads();
        }
    }

    // ---- epilogue ----
#pragma unroll
    for (int i = 0; i < 4; i++) {
        int t = t0 + otr * 4 + i;
        float* Ob = g_o + (size_t)(b * T_SEQ + t) * VDIM + h * DV;
#pragma unroll
        for (int vcid = 0; vcid < 4; vcid++) {
            *(float4*)(Ob + vcid * 128 + occ * 4) =
                make_float4(acc[i][vcid * 4 + 0], acc[i][vcid * 4 + 1],
                            acc[i][vcid * 4 + 2], acc[i][vcid * 4 + 3]);
        }
    }
}

// ---------------------------------------------------------------------------
// RMSNorm over dv=512 (per b,t,h) * g_norm_w * silu(g). In place on g_o.
// One block per (bt, h). 256 threads, 2 elems each.
// ---------------------------------------------------------------------------
__global__ __launch_bounds__(256) void gate_kernel(const float* __restrict__ gw)
{
    __shared__ float ws[8];
    const int blk = blockIdx.x;     // bt*4 + h
    const int tid = threadIdx.x;
    const size_t base = (size_t)(blk >> 2) * VDIM + (size_t)(blk & 3) * DV;

    float2 o2 = *(float2*)(g_o + base + tid * 2);
    float p = o2.x * o2.x + o2.y * o2.y;
#pragma unroll
    for (int off = 16; off > 0; off >>= 1) p += __shfl_xor_sync(0xffffffffu, p, off);
    if ((tid & 31) == 0) ws[tid >> 5] = p;
    __syncthreads();
    float tot = ws[0] + ws[1] + ws[2] + ws[3] + ws[4] + ws[5] + ws[6] + ws[7];
    float rms = rsqrtf(tot * (1.0f / (float)DV) + 1e-5f);

    const int c = tid * 2;
    float2 g2 = *(const float2*)(g_g + base + c);
    float s0 = g2.x / (1.0f + expf(-g2.x));
    float s1 = g2.y / (1.0f + expf(-g2.y));
    o2.x = o2.x * rms * gw[c] * s0;
    o2.y = o2.y * rms * gw[c + 1] * s1;
    *(float2*)(g_o + base + c) = o2;
}

// ---------------------------------------------------------------------------
extern "C" void kernel_launch(void* const* d_in, const int* in_sizes, int n_in,
                              void* d_out, int out_size)
{
    const float* x  = (const float*)d_in[0];
    const float* Wq = (const float*)d_in[1];
    const float* Wk = (const float*)d_in[2];
    const float* Wv = (const float*)d_in[3];
    const float* Wg = (const float*)d_in[4];
    const float* Wo = (const float*)d_in[5];
    const float* gw = (const float*)d_in[6];
    float* out = (float*)d_out;

    dim3 gqk(KDIM / 128, MROWS / 128);   // (8, 32)
    dim3 gvg(VDIM / 128, MROWS / 128);   // (16, 32)
    dim3 gout(DMODEL / 128, MROWS / 128);

    // Projections
    sgemm_nt<<<gqk, 256>>>(x, -1, Wq, nullptr, 0, MROWS, KDIM, DMODEL);  // -> g_q
    sgemm_nt<<<gqk, 256>>>(x, -1, Wk, nullptr, 1, MROWS, KDIM, DMODEL);  // -> g_k
    sgemm_nt<<<gvg, 256>>>(x, -1, Wv, nullptr, 2, MROWS, VDIM, DMODEL);  // -> g_v
    sgemm_nt<<<gvg, 256>>>(x, -1, Wg, nullptr, 3, MROWS, VDIM, DMODEL);  // -> g_g

    // RoPE + q scaling
    rope_kernel<<<(NB * T_SEQ * NH * 128) / 256, 256>>>();

    // Retention attention
    dim3 ga(T_SEQ / BM, NB * NH);        // (64, 8)
    retention_attn<<<ga, 256>>>();

    // RMSNorm + gate
    gate_kernel<<<MROWS * NH, 256>>>(gw);

    // Output projection
    sgemm_nt<<<gout, 256>>>(nullptr, 4, Wo, out, -1, MROWS, DMODEL, VDIM);
}

// round 2
// speedup vs baseline: 1.9140x; 1.9140x over previous
#include <cuda_runtime.h>
#include <math.h>
#include <stdint.h>

// Problem constants
constexpr int T_SEQ  = 2048;
constexpr int NB     = 2;
constexpr int NH     = 4;
constexpr int DK     = 256;
constexpr int DV     = 512;
constexpr int DMODEL = 1024;
constexpr int KDIM   = NH * DK;    // 1024
constexpr int VDIM   = NH * DV;    // 2048
constexpr int MROWS  = NB * T_SEQ; // 4096

// Scratch (device globals; no allocations allowed)
__device__ __align__(128) float g_q[MROWS * KDIM];
__device__ __align__(128) float g_k[MROWS * KDIM];
__device__ __align__(128) float g_v[MROWS * VDIM];
__device__ __align__(128) float g_g[MROWS * VDIM];
__device__ __align__(128) float g_o[MROWS * VDIM];

__device__ __forceinline__ float* scratch_ptr(int sel) {
    switch (sel) {
        case 0: return g_q;
        case 1: return g_k;
        case 2: return g_v;
        case 3: return g_g;
        case 4: return g_o;
    }
    return nullptr;
}

__device__ __forceinline__ unsigned f2tf(float f) {
    unsigned u;
    asm("cvt.rna.tf32.f32 %0, %1;" : "=r"(u) : "f"(f));
    return u;
}

// mma.sync m16n8k8 tf32: D += A*B, fp32 accumulate
__device__ __forceinline__ void mma_tf32(float* c, const unsigned* a, const unsigned* b) {
    asm volatile(
        "mma.sync.aligned.m16n8k8.row.col.f32.tf32.tf32.f32 "
        "{%0,%1,%2,%3}, {%4,%5,%6,%7}, {%8,%9}, {%0,%1,%2,%3};\n"
        : "+f"(c[0]), "+f"(c[1]), "+f"(c[2]), "+f"(c[3])
        : "r"(a[0]), "r"(a[1]), "r"(a[2]), "r"(a[3]), "r"(b[0]), "r"(b[1]));
}

// ---------------------------------------------------------------------------
// TF32 GEMM: C[M,N] = A[M,K] @ W[N,K]^T (row-major, K contiguous).
// 128x128 tile, BK=32, 256 threads, 8 warps: warp grid 4(m) x 2(n), 32x64.
// ---------------------------------------------------------------------------
__global__ __launch_bounds__(256) void gemm_tf32(
    const float* __restrict__ Aext, int asel,
    const float* __restrict__ W,
    float* __restrict__ Cext, int csel,
    int M, int N, int K)
{
    const float* A = (asel >= 0) ? scratch_ptr(asel) : Aext;
    float* C       = (csel >= 0) ? scratch_ptr(csel) : Cext;

    __shared__ unsigned As[128 * 36];
    __shared__ unsigned Bs[128 * 36];

    const int bm = blockIdx.y * 128;
    const int bn = blockIdx.x * 128;
    const int tid  = threadIdx.x;
    const int lane = tid & 31;
    const int wid  = tid >> 5;
    const int wm = (wid & 3) * 32;
    const int wn = (wid >> 2) * 64;
    const int gq = lane >> 2;
    const int tq = lane & 3;

    float acc[2][8][4];
#pragma unroll
    for (int mt = 0; mt < 2; mt++)
#pragma unroll
        for (int nt = 0; nt < 8; nt++)
#pragma unroll
            for (int e = 0; e < 4; e++) acc[mt][nt][e] = 0.0f;

    for (int k0 = 0; k0 < K; k0 += 32) {
#pragma unroll
        for (int i = 0; i < 4; i++) {
            int id  = i * 256 + tid;
            int row = id >> 3;
            int kq  = (id & 7) * 4;
            float4 a = *(const float4*)(A + (size_t)(bm + row) * K + k0 + kq);
            *(uint4*)&As[row * 36 + kq] =
                make_uint4(f2tf(a.x), f2tf(a.y), f2tf(a.z), f2tf(a.w));
            float4 b = *(const float4*)(W + (size_t)(bn + row) * K + k0 + kq);
            *(uint4*)&Bs[row * 36 + kq] =
                make_uint4(f2tf(b.x), f2tf(b.y), f2tf(b.z), f2tf(b.w));
        }
        __syncthreads();
#pragma unroll
        for (int kk = 0; kk < 32; kk += 8) {
            unsigned af[2][4];
#pragma unroll
            for (int mt = 0; mt < 2; mt++) {
                int r = wm + mt * 16 + gq;
                af[mt][0] = As[r * 36 + kk + tq];
                af[mt][1] = As[(r + 8) * 36 + kk + tq];
                af[mt][2] = As[r * 36 + kk + 4 + tq];
                af[mt][3] = As[(r + 8) * 36 + kk + 4 + tq];
            }
#pragma unroll
            for (int nt = 0; nt < 8; nt++) {
                int c = wn + nt * 8 + gq;
                unsigned bf[2];
                bf[0] = Bs[c * 36 + kk + tq];
                bf[1] = Bs[c * 36 + kk + 4 + tq];
#pragma unroll
                for (int mt = 0; mt < 2; mt++)
                    mma_tf32(acc[mt][nt], af[mt], bf);
            }
        }
        __syncthreads();
    }

#pragma unroll
    for (int mt = 0; mt < 2; mt++) {
        int r0 = bm + wm + mt * 16 + gq;
#pragma unroll
        for (int nt = 0; nt < 8; nt++) {
            int cc = bn + wn + nt * 8 + tq * 2;
            *(float2*)(C + (size_t)r0 * N + cc)       = make_float2(acc[mt][nt][0], acc[mt][nt][1]);
            *(float2*)(C + (size_t)(r0 + 8) * N + cc) = make_float2(acc[mt][nt][2], acc[mt][nt][3]);
        }
    }
}

// ---------------------------------------------------------------------------
// RoPE (in place on g_q, g_k) + q scale by dk^-0.5 (fp32 path as reference).
// ---------------------------------------------------------------------------
__global__ __launch_bounds__(256) void rope_kernel()
{
    int idx = blockIdx.x * 256 + threadIdx.x;
    int i  = idx & 127;
    int h  = (idx >> 7) & 3;
    int bt = idx >> 9;
    int t  = bt & (T_SEQ - 1);
    size_t base = (size_t)bt * KDIM + h * DK;

    float e    = (float)(2 * i) * (1.0f / 256.0f);
    float invf = 1.0f / powf(10000.0f, e);
    float ang  = (float)t * invf;
    float sn, cs;
    sincosf(ang, &sn, &cs);

    float q1 = g_q[base + i], q2 = g_q[base + 128 + i];
    g_q[base + i]       = (q1 * cs - q2 * sn) * 0.0625f;
    g_q[base + 128 + i] = (q1 * sn + q2 * cs) * 0.0625f;
    float k1 = g_k[base + i], k2 = g_k[base + 128 + i];
    g_k[base + i]       = k1 * cs - k2 * sn;
    g_k[base + 128 + i] = k1 * sn + k2 * cs;
}

// ---------------------------------------------------------------------------
// Retention attention, tf32 tensor cores.
// BM=32 query rows per CTA, key blocks of BN=64. 256 threads = 8 warps.
// Phase1: S = Q@K^T (warp tile 16x16). Decay+mask -> Ss (tf32).
// Phase2: O += S@V, V transposed to smem per 64-wide dv chunk.
// ---------------------------------------------------------------------------
__global__ __launch_bounds__(256) void retention_attn()
{
    __shared__ unsigned Qs[32 * 36];
    __shared__ unsigned Ks[64 * 36];
    __shared__ unsigned Ss[32 * 68];
    __shared__ unsigned Vs[64 * 68];

    const int tid  = threadIdx.x;
    const int lane = tid & 31;
    const int wid  = tid >> 5;
    const int gq = lane >> 2;
    const int tq = lane & 3;

    const int bh = blockIdx.y;
    const int b  = bh >> 2, h = bh & 3;
    const int t0 = blockIdx.x * 32;

    const float* Qb = g_q + (size_t)(b * T_SEQ) * KDIM + h * DK;
    const float* Kb = g_k + (size_t)(b * T_SEQ) * KDIM + h * DK;
    const float* Vb = g_v + (size_t)(b * T_SEQ) * VDIM + h * DV;

    const float lam = logf(1.0f - exp2f(-5.0f - (float)h));

    const int wrm = (wid & 1) * 16;   // warp row base (both phases)
    const int wcn = (wid >> 1) * 16;  // warp col base (both phases)

    float oacc[8][2][4];
#pragma unroll
    for (int ch = 0; ch < 8; ch++)
#pragma unroll
        for (int nt = 0; nt < 2; nt++)
#pragma unroll
            for (int e = 0; e < 4; e++) oacc[ch][nt][e] = 0.0f;

    for (int s0 = 0; s0 < t0 + 32; s0 += 64) {
        // ---------------- Phase 1: S = Q @ K^T ----------------
        float sacc[2][4] = {{0.f,0.f,0.f,0.f},{0.f,0.f,0.f,0.f}};

        for (int kc = 0; kc < DK; kc += 32) {
            {
                int row = tid >> 3, kq = (tid & 7) * 4;
                float4 q = *(const float4*)(Qb + (size_t)(t0 + row) * KDIM + kc + kq);
                *(uint4*)&Qs[row * 36 + kq] =
                    make_uint4(f2tf(q.x), f2tf(q.y), f2tf(q.z), f2tf(q.w));
            }
#pragma unroll
            for (int i = 0; i < 2; i++) {
                int id = i * 256 + tid;
                int row = id >> 3, kq = (id & 7) * 4;
                float4 kv = *(const float4*)(Kb + (size_t)(s0 + row) * KDIM + kc + kq);
                *(uint4*)&Ks[row * 36 + kq] =
                    make_uint4(f2tf(kv.x), f2tf(kv.y), f2tf(kv.z), f2tf(kv.w));
            }
            __syncthreads();
#pragma unroll
            for (int kk = 0; kk < 32; kk += 8) {
                unsigned af[4];
                int r = wrm + gq;
                af[0] = Qs[r * 36 + kk + tq];
                af[1] = Qs[(r + 8) * 36 + kk + tq];
                af[2] = Qs[r * 36 + kk + 4 + tq];
                af[3] = Qs[(r + 8) * 36 + kk + 4 + tq];
#pragma unroll
                for (int nt = 0; nt < 2; nt++) {
                    int c = wcn + nt * 8 + gq;
                    unsigned bf[2];
                    bf[0] = Ks[c * 36 + kk + tq];
                    bf[1] = Ks[c * 36 + kk + 4 + tq];
                    mma_tf32(sacc[nt], af, bf);
                }
            }
            __syncthreads();
        }

        // decay + causal mask -> Ss as tf32
#pragma unroll
        for (int nt = 0; nt < 2; nt++) {
#pragma unroll
            for (int e = 0; e < 4; e++) {
                int r = wrm + gq + (e >> 1) * 8;
                int c = wcn + nt * 8 + tq * 2 + (e & 1);
                int t = t0 + r, s = s0 + c;
                float w = (t >= s) ? __expf(lam * (float)(t - s)) : 0.0f;
                Ss[r * 68 + c] = f2tf(sacc[nt][e] * w);
            }
        }
        __syncthreads();

        // preload S a-fragments for all k (64)
        unsigned af2[8][4];
        {
            int r = wrm + gq;
#pragma unroll
            for (int k8 = 0; k8 < 8; k8++) {
                int kk = k8 * 8;
                af2[k8][0] = Ss[r * 68 + kk + tq];
                af2[k8][1] = Ss[(r + 8) * 68 + kk + tq];
                af2[k8][2] = Ss[r * 68 + kk + 4 + tq];
                af2[k8][3] = Ss[(r + 8) * 68 + kk + 4 + tq];
            }
        }

        // ---------------- Phase 2: O += S @ V ----------------
#pragma unroll
        for (int ch = 0; ch < 8; ch++) {
            __syncthreads();
#pragma unroll
            for (int i = 0; i < 4; i++) {
                int id = i * 256 + tid;
                int c  = id & 63;
                int sg = (id >> 6) * 4;
                const float* vp = Vb + (size_t)(s0 + sg) * VDIM + ch * 64 + c;
                *(uint4*)&Vs[c * 68 + sg] = make_uint4(
                    f2tf(vp[0]), f2tf(vp[VDIM]), f2tf(vp[2 * VDIM]), f2tf(vp[3 * VDIM]));
            }
            __syncthreads();
#pragma unroll
            for (int k8 = 0; k8 < 8; k8++) {
                int kk = k8 * 8;
#pragma unroll
                for (int nt = 0; nt < 2; nt++) {
                    int c = wcn + nt * 8 + gq;
                    unsigned bf[2];
                    bf[0] = Vs[c * 68 + kk + tq];
                    bf[1] = Vs[c * 68 + kk + 4 + tq];
                    mma_tf32(oacc[ch][nt], af2[k8], bf);
                }
            }
        }
    }

    // epilogue: write O (fp32)
#pragma unroll
    for (int ch = 0; ch < 8; ch++) {
#pragma unroll
        for (int nt = 0; nt < 2; nt++) {
            int r = t0 + wrm + gq;
            int c = h * DV + ch * 64 + wcn + nt * 8 + tq * 2;
            *(float2*)(g_o + (size_t)(b * T_SEQ + r) * VDIM + c) =
                make_float2(oacc[ch][nt][0], oacc[ch][nt][1]);
            *(float2*)(g_o + (size_t)(b * T_SEQ + r + 8) * VDIM + c) =
                make_float2(oacc[ch][nt][2], oacc[ch][nt][3]);
        }
    }
}

// ---------------------------------------------------------------------------
// RMSNorm over dv=512 (per b,t,h) * g_norm_w * silu(g). In place on g_o.
// ---------------------------------------------------------------------------
__global__ __launch_bounds__(256) void gate_kernel(const float* __restrict__ gw)
{
    __shared__ float ws[8];
    const int blk = blockIdx.x;     // bt*4 + h
    const int tid = threadIdx.x;
    const size_t base = (size_t)(blk >> 2) * VDIM + (size_t)(blk & 3) * DV;

    float2 o2 = *(float2*)(g_o + base + tid * 2);
    float p = o2.x * o2.x + o2.y * o2.y;
#pragma unroll
    for (int off = 16; off > 0; off >>= 1) p += __shfl_xor_sync(0xffffffffu, p, off);
    if ((tid & 31) == 0) ws[tid >> 5] = p;
    __syncthreads();
    float tot = ws[0] + ws[1] + ws[2] + ws[3] + ws[4] + ws[5] + ws[6] + ws[7];
    float rms = rsqrtf(tot * (1.0f / (float)DV) + 1e-5f);

    const int c = tid * 2;
    float2 g2 = *(const float2*)(g_g + base + c);
    float s0 = g2.x / (1.0f + expf(-g2.x));
    float s1 = g2.y / (1.0f + expf(-g2.y));
    o2.x = o2.x * rms * gw[c] * s0;
    o2.y = o2.y * rms * gw[c + 1] * s1;
    *(float2*)(g_o + base + c) = o2;
}

// ---------------------------------------------------------------------------
extern "C" void kernel_launch(void* const* d_in, const int* in_sizes, int n_in,
                              void* d_out, int out_size)
{
    const float* x  = (const float*)d_in[0];
    const float* Wq = (const float*)d_in[1];
    const float* Wk = (const float*)d_in[2];
    const float* Wv = (const float*)d_in[3];
    const float* Wg = (const float*)d_in[4];
    const float* Wo = (const float*)d_in[5];
    const float* gw = (const float*)d_in[6];
    float* out = (float*)d_out;

    dim3 gqk(KDIM / 128, MROWS / 128);   // (8, 32)
    dim3 gvg(VDIM / 128, MROWS / 128);   // (16, 32)
    dim3 gout(DMODEL / 128, MROWS / 128);

    gemm_tf32<<<gqk, 256>>>(x, -1, Wq, nullptr, 0, MROWS, KDIM, DMODEL);  // -> g_q
    gemm_tf32<<<gqk, 256>>>(x, -1, Wk, nullptr, 1, MROWS, KDIM, DMODEL);  // -> g_k
    gemm_tf32<<<gvg, 256>>>(x, -1, Wv, nullptr, 2, MROWS, VDIM, DMODEL);  // -> g_v
    gemm_tf32<<<gvg, 256>>>(x, -1, Wg, nullptr, 3, MROWS, VDIM, DMODEL);  // -> g_g

    rope_kernel<<<(NB * T_SEQ * NH * 128) / 256, 256>>>();

    dim3 ga(T_SEQ / 32, NB * NH);        // (64, 8)
    retention_attn<<<ga, 256>>>();

    gate_kernel<<<MROWS * NH, 256>>>(gw);

    gemm_tf32<<<gout, 256>>>(nullptr, 4, Wo, out, -1, MROWS, DMODEL, VDIM);
}

// round 3
// speedup vs baseline: 4.6371x; 2.4228x over previous
#include <cuda_runtime.h>
#include <math.h>
#include <stdint.h>

// Problem constants
constexpr int T_SEQ  = 2048;
constexpr int NB     = 2;
constexpr int NH     = 4;
constexpr int DK     = 256;
constexpr int DV     = 512;
constexpr int DMODEL = 1024;
constexpr int KDIM   = NH * DK;    // 1024
constexpr int VDIM   = NH * DV;    // 2048
constexpr int MROWS  = NB * T_SEQ; // 4096
constexpr int CHK    = 128;        // chunk length
constexpr int NCH    = T_SEQ / CHK; // 16
constexpr int STSZ   = DV * DK;    // 131072 floats per state

// Scratch (device globals; no allocations allowed)
__device__ __align__(128) float g_q[MROWS * KDIM];
__device__ __align__(128) float g_k[MROWS * KDIM];
__device__ __align__(128) float g_v[MROWS * VDIM];
__device__ __align__(128) float g_g[MROWS * VDIM];
__device__ __align__(128) float g_o[MROWS * VDIM];
__device__ __align__(128) float g_state[NB * NH * NCH * STSZ]; // 67 MB

__device__ __forceinline__ float* scratch_ptr(int sel) {
    switch (sel) {
        case 0: return g_q;
        case 1: return g_k;
        case 2: return g_v;
        case 3: return g_g;
        case 4: return g_o;
    }
    return nullptr;
}

__device__ __forceinline__ unsigned f2tf(float f) {
    unsigned u;
    asm("cvt.rna.tf32.f32 %0, %1;" : "=r"(u) : "f"(f));
    return u;
}

__device__ __forceinline__ void mma_tf32(float* c, const unsigned* a, const unsigned* b) {
    asm volatile(
        "mma.sync.aligned.m16n8k8.row.col.f32.tf32.tf32.f32 "
        "{%0,%1,%2,%3}, {%4,%5,%6,%7}, {%8,%9}, {%0,%1,%2,%3};\n"
        : "+f"(c[0]), "+f"(c[1]), "+f"(c[2]), "+f"(c[3])
        : "r"(a[0]), "r"(a[1]), "r"(a[2]), "r"(a[3]), "r"(b[0]), "r"(b[1]));
}

__device__ __forceinline__ float head_lam(int h) {
    return logf(1.0f - exp2f(-5.0f - (float)h));
}

// ---------------------------------------------------------------------------
// TF32 GEMM: C[M,N] = A[M,K] @ W[N,K]^T (row-major, K contiguous).
// 128x128 tile, BK=32, 256 threads, warp grid 4(m) x 2(n), warp tile 32x64.
// ---------------------------------------------------------------------------
__global__ __launch_bounds__(256) void gemm_tf32(
    const float* __restrict__ Aext, int asel,
    const float* __restrict__ W,
    float* __restrict__ Cext, int csel,
    int M, int N, int K)
{
    const float* A = (asel >= 0) ? scratch_ptr(asel) : Aext;
    float* C       = (csel >= 0) ? scratch_ptr(csel) : Cext;

    __shared__ unsigned As[128 * 36];
    __shared__ unsigned Bs[128 * 36];

    const int bm = blockIdx.y * 128;
    const int bn = blockIdx.x * 128;
    const int tid  = threadIdx.x;
    const int lane = tid & 31;
    const int wid  = tid >> 5;
    const int wm = (wid & 3) * 32;
    const int wn = (wid >> 2) * 64;
    const int gq = lane >> 2;
    const int tq = lane & 3;

    float acc[2][8][4];
#pragma unroll
    for (int mt = 0; mt < 2; mt++)
#pragma unroll
        for (int nt = 0; nt < 8; nt++)
#pragma unroll
            for (int e = 0; e < 4; e++) acc[mt][nt][e] = 0.0f;

    for (int k0 = 0; k0 < K; k0 += 32) {
#pragma unroll
        for (int i = 0; i < 4; i++) {
            int id  = i * 256 + tid;
            int row = id >> 3;
            int kq  = (id & 7) * 4;
            float4 a = *(const float4*)(A + (size_t)(bm + row) * K + k0 + kq);
            *(uint4*)&As[row * 36 + kq] =
                make_uint4(f2tf(a.x), f2tf(a.y), f2tf(a.z), f2tf(a.w));
            float4 b = *(const float4*)(W + (size_t)(bn + row) * K + k0 + kq);
            *(uint4*)&Bs[row * 36 + kq] =
                make_uint4(f2tf(b.x), f2tf(b.y), f2tf(b.z), f2tf(b.w));
        }
        __syncthreads();
#pragma unroll
        for (int kk = 0; kk < 32; kk += 8) {
            unsigned af[2][4];
#pragma unroll
            for (int mt = 0; mt < 2; mt++) {
                int r = wm + mt * 16 + gq;
                af[mt][0] = As[r * 36 + kk + tq];
                af[mt][1] = As[(r + 8) * 36 + kk + tq];
                af[mt][2] = As[r * 36 + kk + 4 + tq];
                af[mt][3] = As[(r + 8) * 36 + kk + 4 + tq];
            }
#pragma unroll
            for (int nt = 0; nt < 8; nt++) {
                int c = wn + nt * 8 + gq;
                unsigned bf[2];
                bf[0] = Bs[c * 36 + kk + tq];
                bf[1] = Bs[c * 36 + kk + 4 + tq];
#pragma unroll
                for (int mt = 0; mt < 2; mt++)
                    mma_tf32(acc[mt][nt], af[mt], bf);
            }
        }
        __syncthreads();
    }

#pragma unroll
    for (int mt = 0; mt < 2; mt++) {
        int r0 = bm + wm + mt * 16 + gq;
#pragma unroll
        for (int nt = 0; nt < 8; nt++) {
            int cc = bn + wn + nt * 8 + tq * 2;
            *(float2*)(C + (size_t)r0 * N + cc)       = make_float2(acc[mt][nt][0], acc[mt][nt][1]);
            *(float2*)(C + (size_t)(r0 + 8) * N + cc) = make_float2(acc[mt][nt][2], acc[mt][nt][3]);
        }
    }
}

// ---------------------------------------------------------------------------
// RoPE (in place on g_q, g_k) + q scale by dk^-0.5 (fp32 path as reference).
// ---------------------------------------------------------------------------
__global__ __launch_bounds__(256) void rope_kernel()
{
    int idx = blockIdx.x * 256 + threadIdx.x;
    int i  = idx & 127;
    int h  = (idx >> 7) & 3;
    int bt = idx >> 9;
    int t  = bt & (T_SEQ - 1);
    size_t base = (size_t)bt * KDIM + h * DK;

    float e    = (float)(2 * i) * (1.0f / 256.0f);
    float invf = 1.0f / powf(10000.0f, e);
    float ang  = (float)t * invf;
    float sn, cs;
    sincosf(ang, &sn, &cs);

    float q1 = g_q[base + i], q2 = g_q[base + 128 + i];
    g_q[base + i]       = (q1 * cs - q2 * sn) * 0.0625f;
    g_q[base + 128 + i] = (q1 * sn + q2 * cs) * 0.0625f;
    float k1 = g_k[base + i], k2 = g_k[base + 128 + i];
    g_k[base + i]       = k1 * cs - k2 * sn;
    g_k[base + 128 + i] = k1 * sn + k2 * cs;
}

// ---------------------------------------------------------------------------
// Phase A: per (bh, chunk) compute U^T[dv, dk] = sum_i lam^(C-i) V[i,:]^T K[i,:]
// TN gemm, k = 128 (chunk positions), done in two 64-halves.
// Grid: x = dvt(4) + 4*dkt(2) -> 8, y = chunk (16), z = bh (8).
// ---------------------------------------------------------------------------
__global__ __launch_bounds__(256) void chunk_kv()
{
    extern __shared__ unsigned pool[];
    unsigned* Vt = pool;          // [128 dv][68]
    unsigned* Kt = pool + 8704;   // [128 dk][68]

    const int tid  = threadIdx.x;
    const int lane = tid & 31;
    const int wid  = tid >> 5;
    const int gq = lane >> 2;
    const int tq = lane & 3;
    const int wm = (wid & 3) * 32;   // dv
    const int wn = (wid >> 2) * 64;  // dk

    const int dvt = blockIdx.x & 3;
    const int dkt = blockIdx.x >> 2;
    const int c   = blockIdx.y;
    const int bh  = blockIdx.z;
    const int b = bh >> 2, h = bh & 3;
    const float lam = head_lam(h);

    const int rowbase = b * T_SEQ + c * CHK;
    const float* Vb = g_v + (size_t)rowbase * VDIM + h * DV + dvt * 128;
    const float* Kb = g_k + (size_t)rowbase * KDIM + h * DK + dkt * 128;

    float acc[2][8][4];
#pragma unroll
    for (int mt = 0; mt < 2; mt++)
#pragma unroll
        for (int nt = 0; nt < 8; nt++)
#pragma unroll
            for (int e = 0; e < 4; e++) acc[mt][nt][e] = 0.0f;

    for (int sh = 0; sh < 2; sh++) {
        // load V^T and Khat^T tiles (transpose via scattered STS)
#pragma unroll
        for (int it = 0; it < 8; it++) {
            int id = it * 256 + tid;
            int n4 = id & 31;
            int i  = id >> 5;              // 0..63
            float4 v = *(const float4*)(Vb + (size_t)(sh * 64 + i) * VDIM + n4 * 4);
            Vt[(n4 * 4 + 0) * 68 + i] = f2tf(v.x);
            Vt[(n4 * 4 + 1) * 68 + i] = f2tf(v.y);
            Vt[(n4 * 4 + 2) * 68 + i] = f2tf(v.z);
            Vt[(n4 * 4 + 3) * 68 + i] = f2tf(v.w);
            float w = expf(lam * (float)(CHK - (sh * 64 + i)));
            float4 kv = *(const float4*)(Kb + (size_t)(sh * 64 + i) * KDIM + n4 * 4);
            Kt[(n4 * 4 + 0) * 68 + i] = f2tf(kv.x * w);
            Kt[(n4 * 4 + 1) * 68 + i] = f2tf(kv.y * w);
            Kt[(n4 * 4 + 2) * 68 + i] = f2tf(kv.z * w);
            Kt[(n4 * 4 + 3) * 68 + i] = f2tf(kv.w * w);
        }
        __syncthreads();
#pragma unroll
        for (int kk = 0; kk < 64; kk += 8) {
            unsigned af[2][4];
#pragma unroll
            for (int mt = 0; mt < 2; mt++) {
                int r = wm + mt * 16 + gq;
                af[mt][0] = Vt[r * 68 + kk + tq];
                af[mt][1] = Vt[(r + 8) * 68 + kk + tq];
                af[mt][2] = Vt[r * 68 + kk + 4 + tq];
                af[mt][3] = Vt[(r + 8) * 68 + kk + 4 + tq];
            }
#pragma unroll
            for (int nt = 0; nt < 8; nt++) {
                int cc = wn + nt * 8 + gq;
                unsigned bf[2];
                bf[0] = Kt[cc * 68 + kk + tq];
                bf[1] = Kt[cc * 68 + kk + 4 + tq];
#pragma unroll
                for (int mt = 0; mt < 2; mt++)
                    mma_tf32(acc[mt][nt], af[mt], bf);
            }
        }
        __syncthreads();
    }

    float* St = g_state + (size_t)(bh * NCH + c) * STSZ;
#pragma unroll
    for (int mt = 0; mt < 2; mt++) {
        int r0 = dvt * 128 + wm + mt * 16 + gq;
#pragma unroll
        for (int nt = 0; nt < 8; nt++) {
            int cc = dkt * 128 + wn + nt * 8 + tq * 2;
            *(float2*)(St + (size_t)r0 * DK + cc)       = make_float2(acc[mt][nt][0], acc[mt][nt][1]);
            *(float2*)(St + (size_t)(r0 + 8) * DK + cc) = make_float2(acc[mt][nt][2], acc[mt][nt][3]);
        }
    }
}

// ---------------------------------------------------------------------------
// Phase B: in-place prefix scan over chunks:
//   State_c = lam^C * State_{c-1} + U_{c-1},  State_0 = 0
// One float4 per thread, serial over 16 chunks.
// ---------------------------------------------------------------------------
__global__ __launch_bounds__(256) void state_scan()
{
    int tid4 = blockIdx.x * 256 + threadIdx.x;      // 0 .. 262143
    int bh   = tid4 >> 15;                          // 32768 float4 per bh
    int off  = (tid4 & 32767) * 4;
    const float d = expf(head_lam(bh & 3) * (float)CHK);

    float* base = g_state + (size_t)bh * NCH * STSZ + off;
    float4 s = make_float4(0.f, 0.f, 0.f, 0.f);
#pragma unroll
    for (int c = 0; c < NCH; c++) {
        float4 u = *(float4*)(base + (size_t)c * STSZ);
        *(float4*)(base + (size_t)c * STSZ) = s;
        s.x = d * s.x + u.x;
        s.y = d * s.y + u.y;
        s.z = d * s.z + u.z;
        s.w = d * s.w + u.w;
    }
}

// ---------------------------------------------------------------------------
// Phase C: per (bh, chunk, dv-tile):
//   O[128, 128] = Qhat @ State^T  +  (mask . (Q K^T)) @ V
// Grid: x = dvt (4), y = chunk (16), z = bh (8). 256 threads.
// ---------------------------------------------------------------------------
constexpr int QS_OFF = 0;      // [128][36]
constexpr int BS_OFF = 4608;   // cross: State [128][36]; intra: Ks [64][36]
constexpr int SS_OFF = 9216;   // [128][68]
constexpr int VT_OFF = 17920;  // [128][68]
constexpr int POOLC_WORDS = 26624;

__global__ __launch_bounds__(256) void chunk_out()
{
    extern __shared__ unsigned pool[];
    unsigned* Qs = pool + QS_OFF;
    unsigned* Bs = pool + BS_OFF;
    unsigned* Ss = pool + SS_OFF;
    unsigned* Vt = pool + VT_OFF;

    const int tid  = threadIdx.x;
    const int lane = tid & 31;
    const int wid  = tid >> 5;
    const int gq = lane >> 2;
    const int tq = lane & 3;
    const int wm  = (wid & 3) * 32;    // t rows
    const int wn  = (wid >> 2) * 64;   // dv cols (O phase)
    const int wns = (wid >> 2) * 32;   // s cols (S phase)

    const int dvt = blockIdx.x;
    const int c   = blockIdx.y;
    const int bh  = blockIdx.z;
    const int b = bh >> 2, h = bh & 3;
    const float lam = head_lam(h);

    const int rowbase = b * T_SEQ + c * CHK;
    const float* Qb = g_q + (size_t)rowbase * KDIM + h * DK;
    const float* Kb = g_k + (size_t)rowbase * KDIM + h * DK;
    const float* Vb = g_v + (size_t)rowbase * VDIM + h * DV + dvt * 128;
    const float* St = g_state + (size_t)(bh * NCH + c) * STSZ + (size_t)dvt * 128 * DK;

    float oacc[2][8][4];
#pragma unroll
    for (int mt = 0; mt < 2; mt++)
#pragma unroll
        for (int nt = 0; nt < 8; nt++)
#pragma unroll
            for (int e = 0; e < 4; e++) oacc[mt][nt][e] = 0.0f;

    // ---------------- cross term: O += Qhat @ State^T ----------------
    for (int kc = 0; kc < DK; kc += 32) {
#pragma unroll
        for (int it = 0; it < 4; it++) {
            int id  = it * 256 + tid;
            int row = id >> 3;
            int kq  = (id & 7) * 4;
            float w = expf(lam * (float)row);
            float4 q = *(const float4*)(Qb + (size_t)row * KDIM + kc + kq);
            *(uint4*)&Qs[row * 36 + kq] =
                make_uint4(f2tf(q.x * w), f2tf(q.y * w), f2tf(q.z * w), f2tf(q.w * w));
            float4 s = *(const float4*)(St + (size_t)row * DK + kc + kq);
            *(uint4*)&Bs[row * 36 + kq] =
                make_uint4(f2tf(s.x), f2tf(s.y), f2tf(s.z), f2tf(s.w));
        }
        __syncthreads();
#pragma unroll
        for (int kk = 0; kk < 32; kk += 8) {
            unsigned af[2][4];
#pragma unroll
            for (int mt = 0; mt < 2; mt++) {
                int r = wm + mt * 16 + gq;
                af[mt][0] = Qs[r * 36 + kk + tq];
                af[mt][1] = Qs[(r + 8) * 36 + kk + tq];
                af[mt][2] = Qs[r * 36 + kk + 4 + tq];
                af[mt][3] = Qs[(r + 8) * 36 + kk + 4 + tq];
            }
#pragma unroll
            for (int nt = 0; nt < 8; nt++) {
                int cc = wn + nt * 8 + gq;
                unsigned bf[2];
                bf[0] = Bs[cc * 36 + kk + tq];
                bf[1] = Bs[cc * 36 + kk + 4 + tq];
#pragma unroll
                for (int mt = 0; mt < 2; mt++)
                    mma_tf32(oacc[mt][nt], af[mt], bf);
            }
        }
        __syncthreads();
    }

    // ---------------- intra term, two 64-key halves ----------------
    for (int sh = 0; sh < 2; sh++) {
        float sacc[2][4][4];
#pragma unroll
        for (int mt = 0; mt < 2; mt++)
#pragma unroll
            for (int nt = 0; nt < 4; nt++)
#pragma unroll
                for (int e = 0; e < 4; e++) sacc[mt][nt][e] = 0.0f;

        for (int kc = 0; kc < DK; kc += 32) {
#pragma unroll
            for (int it = 0; it < 4; it++) {
                int id  = it * 256 + tid;
                int row = id >> 3;
                int kq  = (id & 7) * 4;
                float4 q = *(const float4*)(Qb + (size_t)row * KDIM + kc + kq);
                *(uint4*)&Qs[row * 36 + kq] =
                    make_uint4(f2tf(q.x), f2tf(q.y), f2tf(q.z), f2tf(q.w));
            }
#pragma unroll
            for (int it = 0; it < 2; it++) {
                int id  = it * 256 + tid;
                int row = id >> 3;          // 0..63
                int kq  = (id & 7) * 4;
                float4 kv = *(const float4*)(Kb + (size_t)(sh * 64 + row) * KDIM + kc + kq);
                *(uint4*)&Bs[row * 36 + kq] =
                    make_uint4(f2tf(kv.x), f2tf(kv.y), f2tf(kv.z), f2tf(kv.w));
            }
            __syncthreads();
#pragma unroll
            for (int kk = 0; kk < 32; kk += 8) {
                unsigned af[2][4];
#pragma unroll
                for (int mt = 0; mt < 2; mt++) {
                    int r = wm + mt * 16 + gq;
                    af[mt][0] = Qs[r * 36 + kk + tq];
                    af[mt][1] = Qs[(r + 8) * 36 + kk + tq];
                    af[mt][2] = Qs[r * 36 + kk + 4 + tq];
                    af[mt][3] = Qs[(r + 8) * 36 + kk + 4 + tq];
                }
#pragma unroll
                for (int nt = 0; nt < 4; nt++) {
                    int cc = wns + nt * 8 + gq;
                    unsigned bf[2];
                    bf[0] = Bs[cc * 36 + kk + tq];
                    bf[1] = Bs[cc * 36 + kk + 4 + tq];
#pragma unroll
                    for (int mt = 0; mt < 2; mt++)
                        mma_tf32(sacc[mt][nt], af[mt], bf);
                }
            }
            __syncthreads();
        }

        // mask + decay -> Ss (tf32)
#pragma unroll
        for (int mt = 0; mt < 2; mt++) {
#pragma unroll
            for (int nt = 0; nt < 4; nt++) {
#pragma unroll
                for (int e = 0; e < 4; e++) {
                    int r  = wm + mt * 16 + gq + (e >> 1) * 8;
                    int cl = wns + nt * 8 + tq * 2 + (e & 1);
                    int s  = sh * 64 + cl;
                    float w = (r >= s) ? expf(lam * (float)(r - s)) : 0.0f;
                    Ss[r * 68 + cl] = f2tf(sacc[mt][nt][e] * w);
                }
            }
        }
        // load V^T tile for this half
#pragma unroll
        for (int it = 0; it < 8; it++) {
            int id = it * 256 + tid;
            int n4 = id & 31;
            int i  = id >> 5;      // 0..63
            float4 v = *(const float4*)(Vb + (size_t)(sh * 64 + i) * VDIM + n4 * 4);
            Vt[(n4 * 4 + 0) * 68 + i] = f2tf(v.x);
            Vt[(n4 * 4 + 1) * 68 + i] = f2tf(v.y);
            Vt[(n4 * 4 + 2) * 68 + i] = f2tf(v.z);
            Vt[(n4 * 4 + 3) * 68 + i] = f2tf(v.w);
        }
        __syncthreads();

        // O += Ss @ Vt  (k = 64)
#pragma unroll
        for (int kk = 0; kk < 64; kk += 8) {
            unsigned af[2][4];
#pragma unroll
            for (int mt = 0; mt < 2; mt++) {
                int r = wm + mt * 16 + gq;
                af[mt][0] = Ss[r * 68 + kk + tq];
                af[mt][1] = Ss[(r + 8) * 68 + kk + tq];
                af[mt][2] = Ss[r * 68 + kk + 4 + tq];
                af[mt][3] = Ss[(r + 8) * 68 + kk + 4 + tq];
            }
#pragma unroll
            for (int nt = 0; nt < 8; nt++) {
                int cc = wn + nt * 8 + gq;
                unsigned bf[2];
                bf[0] = Vt[cc * 68 + kk + tq];
                bf[1] = Vt[cc * 68 + kk + 4 + tq];
#pragma unroll
                for (int mt = 0; mt < 2; mt++)
                    mma_tf32(oacc[mt][nt], af[mt], bf);
            }
        }
        __syncthreads();
    }

    // epilogue
#pragma unroll
    for (int mt = 0; mt < 2; mt++) {
        int r0 = wm + mt * 16 + gq;
#pragma unroll
        for (int nt = 0; nt < 8; nt++) {
            int cc = h * DV + dvt * 128 + wn + nt * 8 + tq * 2;
            size_t row = (size_t)(rowbase + r0);
            *(float2*)(g_o + row * VDIM + cc) =
                make_float2(oacc[mt][nt][0], oacc[mt][nt][1]);
            *(float2*)(g_o + (row + 8) * VDIM + cc) =
                make_float2(oacc[mt][nt][2], oacc[mt][nt][3]);
        }
    }
}

// ---------------------------------------------------------------------------
// RMSNorm over dv=512 (per b,t,h) * g_norm_w * silu(g). In place on g_o.
// ---------------------------------------------------------------------------
__global__ __launch_bounds__(256) void gate_kernel(const float* __restrict__ gw)
{
    __shared__ float ws[8];
    const int blk = blockIdx.x;     // bt*4 + h
    const int tid = threadIdx.x;
    const size_t base = (size_t)(blk >> 2) * VDIM + (size_t)(blk & 3) * DV;

    float2 o2 = *(float2*)(g_o + base + tid * 2);
    float p = o2.x * o2.x + o2.y * o2.y;
#pragma unroll
    for (int off = 16; off > 0; off >>= 1) p += __shfl_xor_sync(0xffffffffu, p, off);
    if ((tid & 31) == 0) ws[tid >> 5] = p;
    __syncthreads();
    float tot = ws[0] + ws[1] + ws[2] + ws[3] + ws[4] + ws[5] + ws[6] + ws[7];
    float rms = rsqrtf(tot * (1.0f / (float)DV) + 1e-5f);

    const int c = tid * 2;
    float2 g2 = *(const float2*)(g_g + base + c);
    float s0 = g2.x / (1.0f + expf(-g2.x));
    float s1 = g2.y / (1.0f + expf(-g2.y));
    o2.x = o2.x * rms * gw[c] * s0;
    o2.y = o2.y * rms * gw[c + 1] * s1;
    *(float2*)(g_o + base + c) = o2;
}

// ---------------------------------------------------------------------------
extern "C" void kernel_launch(void* const* d_in, const int* in_sizes, int n_in,
                              void* d_out, int out_size)
{
    const float* x  = (const float*)d_in[0];
    const float* Wq = (const float*)d_in[1];
    const float* Wk = (const float*)d_in[2];
    const float* Wv = (const float*)d_in[3];
    const float* Wg = (const float*)d_in[4];
    const float* Wo = (const float*)d_in[5];
    const float* gw = (const float*)d_in[6];
    float* out = (float*)d_out;

    // opt into >48KB dynamic smem (runs host-side during capture; not a graph node)
    cudaFuncSetAttribute(chunk_kv,  cudaFuncAttributeMaxDynamicSharedMemorySize, 17408 * 4);
    cudaFuncSetAttribute(chunk_out, cudaFuncAttributeMaxDynamicSharedMemorySize, POOLC_WORDS * 4);

    dim3 gqk(KDIM / 128, MROWS / 128);   // (8, 32)
    dim3 gvg(VDIM / 128, MROWS / 128);   // (16, 32)
    dim3 gout(DMODEL / 128, MROWS / 128);

    gemm_tf32<<<gqk, 256>>>(x, -1, Wq, nullptr, 0, MROWS, KDIM, DMODEL);  // -> g_q
    gemm_tf32<<<gqk, 256>>>(x, -1, Wk, nullptr, 1, MROWS, KDIM, DMODEL);  // -> g_k
    gemm_tf32<<<gvg, 256>>>(x, -1, Wv, nullptr, 2, MROWS, VDIM, DMODEL);  // -> g_v
    gemm_tf32<<<gvg, 256>>>(x, -1, Wg, nullptr, 3, MROWS, VDIM, DMODEL);  // -> g_g

    rope_kernel<<<(NB * T_SEQ * NH * 128) / 256, 256>>>();

    // Phase A: per-chunk K^T V
    dim3 ga(8, NCH, NB * NH);
    chunk_kv<<<ga, 256, 17408 * 4>>>();

    // Phase B: scan U -> State
    state_scan<<<1024, 256>>>();

    // Phase C: outputs
    dim3 gc(4, NCH, NB * NH);
    chunk_out<<<gc, 256, POOLC_WORDS * 4>>>();

    gate_kernel<<<MROWS * NH, 256>>>(gw);

    gemm_tf32<<<gout, 256>>>(nullptr, 4, Wo, out, -1, MROWS, DMODEL, VDIM);
}

// round 4
// speedup vs baseline: 4.9115x; 1.0592x over previous
#include <cuda_runtime.h>
#include <math.h>
#include <stdint.h>

// Problem constants
constexpr int T_SEQ  = 2048;
constexpr int NB     = 2;
constexpr int NH     = 4;
constexpr int DK     = 256;
constexpr int DV     = 512;
constexpr int DMODEL = 1024;
constexpr int KDIM   = NH * DK;    // 1024
constexpr int VDIM   = NH * DV;    // 2048
constexpr int MROWS  = NB * T_SEQ; // 4096
constexpr int CHK    = 128;
constexpr int NCH    = T_SEQ / CHK; // 16
constexpr int STSZ   = DV * DK;     // 131072

// Scratch (device globals; no allocations allowed)
__device__ __align__(128) float g_q[MROWS * KDIM];
__device__ __align__(128) float g_k[MROWS * KDIM];
__device__ __align__(128) float g_v[MROWS * VDIM];
__device__ __align__(128) float g_g[MROWS * VDIM];
__device__ __align__(128) float g_o[MROWS * VDIM];
__device__ __align__(128) float g_x[MROWS * DMODEL];         // rounded x
__device__ __align__(128) float g_w[8 * 1024 * 1024];        // rounded weights
__device__ __align__(128) float g_state[NB * NH * NCH * STSZ];

// weight offsets in g_w (floats)
constexpr long long WQ_OFF = 0;
constexpr long long WK_OFF = 1048576;
constexpr long long WV_OFF = 2097152;
constexpr long long WG_OFF = 4194304;
constexpr long long WO_OFF = 6291456;

__device__ __forceinline__ unsigned f2tf(float f) {
    unsigned u;
    asm("cvt.rna.tf32.f32 %0, %1;" : "=r"(u) : "f"(f));
    return u;
}
__device__ __forceinline__ float roundtf(float f) { return __uint_as_float(f2tf(f)); }

__device__ __forceinline__ void mma_tf32(float* c, const unsigned* a, const unsigned* b) {
    asm volatile(
        "mma.sync.aligned.m16n8k8.row.col.f32.tf32.tf32.f32 "
        "{%0,%1,%2,%3}, {%4,%5,%6,%7}, {%8,%9}, {%0,%1,%2,%3};\n"
        : "+f"(c[0]), "+f"(c[1]), "+f"(c[2]), "+f"(c[3])
        : "r"(a[0]), "r"(a[1]), "r"(a[2]), "r"(a[3]), "r"(b[0]), "r"(b[1]));
}

__device__ __forceinline__ float head_lam(int h) {
    return logf(1.0f - exp2f(-5.0f - (float)h));
}

__device__ __forceinline__ void cpasync16(unsigned dst, const void* src) {
    asm volatile("cp.async.cg.shared.global [%0], [%1], 16;\n" :: "r"(dst), "l"(src));
}
__device__ __forceinline__ void cp_commit() {
    asm volatile("cp.async.commit_group;\n" ::: "memory");
}
__device__ __forceinline__ void cp_wait1() {
    asm volatile("cp.async.wait_group 1;\n" ::: "memory");
}

// ---------------------------------------------------------------------------
// Rounding copy: src (external fp32) -> tf32-rounded scratch (g_x or g_w+off)
// ---------------------------------------------------------------------------
__global__ __launch_bounds__(256) void round_copy(
    const float* __restrict__ src, int dsel, long long doff, int n4)
{
    float* dst = ((dsel == 5) ? g_x : g_w) + doff;
    int i = blockIdx.x * 256 + threadIdx.x;
    if (i < n4) {
        float4 v = ((const float4*)src)[i];
        ((float4*)dst)[i] = make_float4(roundtf(v.x), roundtf(v.y),
                                        roundtf(v.z), roundtf(v.w));
    }
}

// ---------------------------------------------------------------------------
// Pipelined TF32 GEMM core: C128x128 tile, BK=32, 3-stage cp.async.
// Inputs MUST already be tf32-rounded. Ab = A block row base, Wb = W block
// row base (output-col-major rows, K contiguous), Cb = output tile base.
// ---------------------------------------------------------------------------
constexpr int TILE_W = 128 * 36;      // words per (A or B) stage buffer
constexpr int GEMM_SMEM = 3 * 2 * TILE_W * 4;  // 110592 bytes

__device__ __forceinline__ void gemm_pipe(
    const float* __restrict__ Ab, const float* __restrict__ Wb,
    float* __restrict__ Cb, int ldc, int K, int roundC, unsigned* smem)
{
    const int tid  = threadIdx.x;
    const int lane = tid & 31;
    const int wid  = tid >> 5;
    const int wm = (wid & 3) * 32;
    const int wn = (wid >> 2) * 64;
    const int gq = lane >> 2;
    const int tq = lane & 3;
    const int nk = K >> 5;

    float acc[2][8][4];
#pragma unroll
    for (int mt = 0; mt < 2; mt++)
#pragma unroll
        for (int nt = 0; nt < 8; nt++)
#pragma unroll
            for (int e = 0; e < 4; e++) acc[mt][nt][e] = 0.0f;

    // prologue: stages 0,1
#pragma unroll
    for (int s = 0; s < 2; s++) {
        unsigned* As = smem + s * 2 * TILE_W;
        unsigned* Bs = As + TILE_W;
        int k0 = s * 32;
#pragma unroll
        for (int i = 0; i < 4; i++) {
            int id = i * 256 + tid;
            int row = id >> 3;
            int kq  = (id & 7) * 4;
            cpasync16((unsigned)__cvta_generic_to_shared(&As[row * 36 + kq]),
                      Ab + (size_t)row * K + k0 + kq);
            cpasync16((unsigned)__cvta_generic_to_shared(&Bs[row * 36 + kq]),
                      Wb + (size_t)row * K + k0 + kq);
        }
        cp_commit();
    }

    for (int j = 0; j < nk; j++) {
        cp_wait1();
        __syncthreads();

        // issue stage j+2 (buffer computed at iter j-1; safe after the sync)
        if (j + 2 < nk) {
            int st = (j + 2) % 3;
            unsigned* As = smem + st * 2 * TILE_W;
            unsigned* Bs = As + TILE_W;
            int k0 = (j + 2) * 32;
#pragma unroll
            for (int i = 0; i < 4; i++) {
                int id = i * 256 + tid;
                int row = id >> 3;
                int kq  = (id & 7) * 4;
                cpasync16((unsigned)__cvta_generic_to_shared(&As[row * 36 + kq]),
                          Ab + (size_t)row * K + k0 + kq);
                cpasync16((unsigned)__cvta_generic_to_shared(&Bs[row * 36 + kq]),
                          Wb + (size_t)row * K + k0 + kq);
            }
        }
        cp_commit();

        unsigned* As = smem + (j % 3) * 2 * TILE_W;
        unsigned* Bs = As + TILE_W;
#pragma unroll
        for (int kk = 0; kk < 32; kk += 8) {
            unsigned af[2][4];
#pragma unroll
            for (int mt = 0; mt < 2; mt++) {
                int r = wm + mt * 16 + gq;
                af[mt][0] = As[r * 36 + kk + tq];
                af[mt][1] = As[(r + 8) * 36 + kk + tq];
                af[mt][2] = As[r * 36 + kk + 4 + tq];
                af[mt][3] = As[(r + 8) * 36 + kk + 4 + tq];
            }
#pragma unroll
            for (int nt = 0; nt < 8; nt++) {
                int c = wn + nt * 8 + gq;
                unsigned bf[2];
                bf[0] = Bs[c * 36 + kk + tq];
                bf[1] = Bs[c * 36 + kk + 4 + tq];
#pragma unroll
                for (int mt = 0; mt < 2; mt++)
                    mma_tf32(acc[mt][nt], af[mt], bf);
            }
        }
    }

#pragma unroll
    for (int mt = 0; mt < 2; mt++) {
        int r0 = wm + mt * 16 + gq;
#pragma unroll
        for (int nt = 0; nt < 8; nt++) {
            int cc = wn + nt * 8 + tq * 2;
            float2 v0 = make_float2(acc[mt][nt][0], acc[mt][nt][1]);
            float2 v1 = make_float2(acc[mt][nt][2], acc[mt][nt][3]);
            if (roundC) {
                v0.x = roundtf(v0.x); v0.y = roundtf(v0.y);
                v1.x = roundtf(v1.x); v1.y = roundtf(v1.y);
            }
            *(float2*)(Cb + (size_t)r0 * ldc + cc)       = v0;
            *(float2*)(Cb + (size_t)(r0 + 8) * ldc + cc) = v1;
        }
    }
}

// Fused projections: x @ {Wq,Wk,Wv,Wg}^T. grid.x in [0,48), grid.y in [0,32)
__global__ __launch_bounds__(256) void proj_gemm()
{
    extern __shared__ unsigned smem[];
    const int bnx = blockIdx.x;
    const int bm  = blockIdx.y * 128;

    const float* Wbase;
    float* Cc; int ldc, col, roundC = 0;
    if (bnx < 8)       { Wbase = g_w + WQ_OFF; Cc = g_q; ldc = 1024; col = bnx * 128; }
    else if (bnx < 16) { Wbase = g_w + WK_OFF; Cc = g_k; ldc = 1024; col = (bnx - 8) * 128; }
    else if (bnx < 32) { Wbase = g_w + WV_OFF; Cc = g_v; ldc = 2048; col = (bnx - 16) * 128; roundC = 1; }
    else               { Wbase = g_w + WG_OFF; Cc = g_g; ldc = 2048; col = (bnx - 32) * 128; }

    gemm_pipe(g_x + (size_t)bm * DMODEL,
              Wbase + (size_t)col * DMODEL,
              Cc + (size_t)bm * ldc + col, ldc, DMODEL, roundC, smem);
}

// Output projection: (g_o rounded) @ Wo^T -> out
__global__ __launch_bounds__(256) void out_gemm(float* __restrict__ out)
{
    extern __shared__ unsigned smem[];
    const int bn = blockIdx.x * 128;
    const int bm = blockIdx.y * 128;
    gemm_pipe(g_o + (size_t)bm * VDIM,
              g_w + WO_OFF + (size_t)bn * VDIM,
              out + (size_t)bm * DMODEL + bn, DMODEL, VDIM, 0, smem);
}

// ---------------------------------------------------------------------------
// RoPE (in place on g_q, g_k) + q scale by dk^-0.5 (fp32 path as reference).
// ---------------------------------------------------------------------------
__global__ __launch_bounds__(256) void rope_kernel()
{
    int idx = blockIdx.x * 256 + threadIdx.x;
    int i  = idx & 127;
    int h  = (idx >> 7) & 3;
    int bt = idx >> 9;
    int t  = bt & (T_SEQ - 1);
    size_t base = (size_t)bt * KDIM + h * DK;

    float e    = (float)(2 * i) * (1.0f / 256.0f);
    float invf = 1.0f / powf(10000.0f, e);
    float ang  = (float)t * invf;
    float sn, cs;
    sincosf(ang, &sn, &cs);

    float q1 = g_q[base + i], q2 = g_q[base + 128 + i];
    g_q[base + i]       = (q1 * cs - q2 * sn) * 0.0625f;
    g_q[base + 128 + i] = (q1 * sn + q2 * cs) * 0.0625f;
    float k1 = g_k[base + i], k2 = g_k[base + 128 + i];
    g_k[base + i]       = k1 * cs - k2 * sn;
    g_k[base + 128 + i] = k1 * sn + k2 * cs;
}

// ---------------------------------------------------------------------------
// Phase A: per (bh, chunk) U^T[dv, dk] = sum_i lam^(C-i) V[i,:]^T K[i,:]
// ---------------------------------------------------------------------------
__global__ __launch_bounds__(256) void chunk_kv()
{
    extern __shared__ unsigned pool[];
    unsigned* Vt = pool;          // [128 dv][68]
    unsigned* Kt = pool + 8704;   // [128 dk][68]

    const int tid  = threadIdx.x;
    const int lane = tid & 31;
    const int wid  = tid >> 5;
    const int gq = lane >> 2;
    const int tq = lane & 3;
    const int wm = (wid & 3) * 32;
    const int wn = (wid >> 2) * 64;

    const int dvt = blockIdx.x & 3;
    const int dkt = blockIdx.x >> 2;
    const int c   = blockIdx.y;
    const int bh  = blockIdx.z;
    const int b = bh >> 2, h = bh & 3;
    const float lam = head_lam(h);

    const int rowbase = b * T_SEQ + c * CHK;
    const float* Vb = g_v + (size_t)rowbase * VDIM + h * DV + dvt * 128;
    const float* Kb = g_k + (size_t)rowbase * KDIM + h * DK + dkt * 128;

    float acc[2][8][4];
#pragma unroll
    for (int mt = 0; mt < 2; mt++)
#pragma unroll
        for (int nt = 0; nt < 8; nt++)
#pragma unroll
            for (int e = 0; e < 4; e++) acc[mt][nt][e] = 0.0f;

    for (int sh = 0; sh < 2; sh++) {
#pragma unroll
        for (int it = 0; it < 8; it++) {
            int id = it * 256 + tid;
            int n4 = id & 31;
            int i  = id >> 5;
            float4 v = *(const float4*)(Vb + (size_t)(sh * 64 + i) * VDIM + n4 * 4);
            Vt[(n4 * 4 + 0) * 68 + i] = f2tf(v.x);
            Vt[(n4 * 4 + 1) * 68 + i] = f2tf(v.y);
            Vt[(n4 * 4 + 2) * 68 + i] = f2tf(v.z);
            Vt[(n4 * 4 + 3) * 68 + i] = f2tf(v.w);
            float w = expf(lam * (float)(CHK - (sh * 64 + i)));
            float4 kv = *(const float4*)(Kb + (size_t)(sh * 64 + i) * KDIM + n4 * 4);
            Kt[(n4 * 4 + 0) * 68 + i] = f2tf(kv.x * w);
            Kt[(n4 * 4 + 1) * 68 + i] = f2tf(kv.y * w);
            Kt[(n4 * 4 + 2) * 68 + i] = f2tf(kv.z * w);
            Kt[(n4 * 4 + 3) * 68 + i] = f2tf(kv.w * w);
        }
        __syncthreads();
#pragma unroll
        for (int kk = 0; kk < 64; kk += 8) {
            unsigned af[2][4];
#pragma unroll
            for (int mt = 0; mt < 2; mt++) {
                int r = wm + mt * 16 + gq;
                af[mt][0] = Vt[r * 68 + kk + tq];
                af[mt][1] = Vt[(r + 8) * 68 + kk + tq];
                af[mt][2] = Vt[r * 68 + kk + 4 + tq];
                af[mt][3] = Vt[(r + 8) * 68 + kk + 4 + tq];
            }
#pragma unroll
            for (int nt = 0; nt < 8; nt++) {
                int cc = wn + nt * 8 + gq;
                unsigned bf[2];
                bf[0] = Kt[cc * 68 + kk + tq];
                bf[1] = Kt[cc * 68 + kk + 4 + tq];
#pragma unroll
                for (int mt = 0; mt < 2; mt++)
                    mma_tf32(acc[mt][nt], af[mt], bf);
            }
        }
        __syncthreads();
    }

    float* St = g_state + (size_t)(bh * NCH + c) * STSZ;
#pragma unroll
    for (int mt = 0; mt < 2; mt++) {
        int r0 = dvt * 128 + wm + mt * 16 + gq;
#pragma unroll
        for (int nt = 0; nt < 8; nt++) {
            int cc = dkt * 128 + wn + nt * 8 + tq * 2;
            *(float2*)(St + (size_t)r0 * DK + cc)       = make_float2(acc[mt][nt][0], acc[mt][nt][1]);
            *(float2*)(St + (size_t)(r0 + 8) * DK + cc) = make_float2(acc[mt][nt][2], acc[mt][nt][3]);
        }
    }
}

// ---------------------------------------------------------------------------
// Phase B: prefix scan; stores tf32-rounded State snapshots (accum fp32).
// ---------------------------------------------------------------------------
__global__ __launch_bounds__(256) void state_scan()
{
    int tid4 = blockIdx.x * 256 + threadIdx.x;
    int bh   = tid4 >> 15;
    int off  = (tid4 & 32767) * 4;
    const float d = expf(head_lam(bh & 3) * (float)CHK);

    float* base = g_state + (size_t)bh * NCH * STSZ + off;
    float4 s = make_float4(0.f, 0.f, 0.f, 0.f);
#pragma unroll
    for (int c = 0; c < NCH; c++) {
        float4 u = *(float4*)(base + (size_t)c * STSZ);
        *(float4*)(base + (size_t)c * STSZ) =
            make_float4(roundtf(s.x), roundtf(s.y), roundtf(s.z), roundtf(s.w));
        s.x = d * s.x + u.x;
        s.y = d * s.y + u.y;
        s.z = d * s.z + u.z;
        s.w = d * s.w + u.w;
    }
}

// ---------------------------------------------------------------------------
// Phase C: O[128,128] = Qhat @ State^T + (mask . Q K^T) @ V
// ---------------------------------------------------------------------------
constexpr int QS_OFF = 0;
constexpr int BS_OFF = 4608;
constexpr int SS_OFF = 9216;
constexpr int VT_OFF = 17920;
constexpr int POOLC_WORDS = 26624;

__global__ __launch_bounds__(256) void chunk_out()
{
    extern __shared__ unsigned pool[];
    unsigned* Qs = pool + QS_OFF;
    unsigned* Bs = pool + BS_OFF;
    unsigned* Ss = pool + SS_OFF;
    unsigned* Vt = pool + VT_OFF;

    const int tid  = threadIdx.x;
    const int lane = tid & 31;
    const int wid  = tid >> 5;
    const int gq = lane >> 2;
    const int tq = lane & 3;
    const int wm  = (wid & 3) * 32;
    const int wn  = (wid >> 2) * 64;
    const int wns = (wid >> 2) * 32;

    const int dvt = blockIdx.x;
    const int c   = blockIdx.y;
    const int bh  = blockIdx.z;
    const int b = bh >> 2, h = bh & 3;
    const float lam = head_lam(h);

    const int rowbase = b * T_SEQ + c * CHK;
    const float* Qb = g_q + (size_t)rowbase * KDIM + h * DK;
    const float* Kb = g_k + (size_t)rowbase * KDIM + h * DK;
    const float* Vb = g_v + (size_t)rowbase * VDIM + h * DV + dvt * 128;
    const float* St = g_state + (size_t)(bh * NCH + c) * STSZ + (size_t)dvt * 128 * DK;

    float oacc[2][8][4];
#pragma unroll
    for (int mt = 0; mt < 2; mt++)
#pragma unroll
        for (int nt = 0; nt < 8; nt++)
#pragma unroll
            for (int e = 0; e < 4; e++) oacc[mt][nt][e] = 0.0f;

    // cross term
    for (int kc = 0; kc < DK; kc += 32) {
#pragma unroll
        for (int it = 0; it < 4; it++) {
            int id  = it * 256 + tid;
            int row = id >> 3;
            int kq  = (id & 7) * 4;
            float w = expf(lam * (float)row);
            float4 q = *(const float4*)(Qb + (size_t)row * KDIM + kc + kq);
            *(uint4*)&Qs[row * 36 + kq] =
                make_uint4(f2tf(q.x * w), f2tf(q.y * w), f2tf(q.z * w), f2tf(q.w * w));
            float4 s = *(const float4*)(St + (size_t)row * DK + kc + kq);
            *(uint4*)&Bs[row * 36 + kq] =
                make_uint4(f2tf(s.x), f2tf(s.y), f2tf(s.z), f2tf(s.w));
        }
        __syncthreads();
#pragma unroll
        for (int kk = 0; kk < 32; kk += 8) {
            unsigned af[2][4];
#pragma unroll
            for (int mt = 0; mt < 2; mt++) {
                int r = wm + mt * 16 + gq;
                af[mt][0] = Qs[r * 36 + kk + tq];
                af[mt][1] = Qs[(r + 8) * 36 + kk + tq];
                af[mt][2] = Qs[r * 36 + kk + 4 + tq];
                af[mt][3] = Qs[(r + 8) * 36 + kk + 4 + tq];
            }
#pragma unroll
            for (int nt = 0; nt < 8; nt++) {
                int cc = wn + nt * 8 + gq;
                unsigned bf[2];
                bf[0] = Bs[cc * 36 + kk + tq];
                bf[1] = Bs[cc * 36 + kk + 4 + tq];
#pragma unroll
                for (int mt = 0; mt < 2; mt++)
                    mma_tf32(oacc[mt][nt], af[mt], bf);
            }
        }
        __syncthreads();
    }

    // intra term
    for (int sh = 0; sh < 2; sh++) {
        float sacc[2][4][4];
#pragma unroll
        for (int mt = 0; mt < 2; mt++)
#pragma unroll
            for (int nt = 0; nt < 4; nt++)
#pragma unroll
                for (int e = 0; e < 4; e++) sacc[mt][nt][e] = 0.0f;

        for (int kc = 0; kc < DK; kc += 32) {
#pragma unroll
            for (int it = 0; it < 4; it++) {
                int id  = it * 256 + tid;
                int row = id >> 3;
                int kq  = (id & 7) * 4;
                float4 q = *(const float4*)(Qb + (size_t)row * KDIM + kc + kq);
                *(uint4*)&Qs[row * 36 + kq] =
                    make_uint4(f2tf(q.x), f2tf(q.y), f2tf(q.z), f2tf(q.w));
            }
#pragma unroll
            for (int it = 0; it < 2; it++) {
                int id  = it * 256 + tid;
                int row = id >> 3;
                int kq  = (id & 7) * 4;
                float4 kv = *(const float4*)(Kb + (size_t)(sh * 64 + row) * KDIM + kc + kq);
                *(uint4*)&Bs[row * 36 + kq] =
                    make_uint4(f2tf(kv.x), f2tf(kv.y), f2tf(kv.z), f2tf(kv.w));
            }
            __syncthreads();
#pragma unroll
            for (int kk = 0; kk < 32; kk += 8) {
                unsigned af[2][4];
#pragma unroll
                for (int mt = 0; mt < 2; mt++) {
                    int r = wm + mt * 16 + gq;
                    af[mt][0] = Qs[r * 36 + kk + tq];
                    af[mt][1] = Qs[(r + 8) * 36 + kk + tq];
                    af[mt][2] = Qs[r * 36 + kk + 4 + tq];
                    af[mt][3] = Qs[(r + 8) * 36 + kk + 4 + tq];
                }
#pragma unroll
                for (int nt = 0; nt < 4; nt++) {
                    int cc = wns + nt * 8 + gq;
                    unsigned bf[2];
                    bf[0] = Bs[cc * 36 + kk + tq];
                    bf[1] = Bs[cc * 36 + kk + 4 + tq];
#pragma unroll
                    for (int mt = 0; mt < 2; mt++)
                        mma_tf32(sacc[mt][nt], af[mt], bf);
                }
            }
            __syncthreads();
        }

#pragma unroll
        for (int mt = 0; mt < 2; mt++) {
#pragma unroll
            for (int nt = 0; nt < 4; nt++) {
#pragma unroll
                for (int e = 0; e < 4; e++) {
                    int r  = wm + mt * 16 + gq + (e >> 1) * 8;
                    int cl = wns + nt * 8 + tq * 2 + (e & 1);
                    int s  = sh * 64 + cl;
                    float w = (r >= s) ? expf(lam * (float)(r - s)) : 0.0f;
                    Ss[r * 68 + cl] = f2tf(sacc[mt][nt][e] * w);
                }
            }
        }
#pragma unroll
        for (int it = 0; it < 8; it++) {
            int id = it * 256 + tid;
            int n4 = id & 31;
            int i  = id >> 5;
            float4 v = *(const float4*)(Vb + (size_t)(sh * 64 + i) * VDIM + n4 * 4);
            Vt[(n4 * 4 + 0) * 68 + i] = f2tf(v.x);
            Vt[(n4 * 4 + 1) * 68 + i] = f2tf(v.y);
            Vt[(n4 * 4 + 2) * 68 + i] = f2tf(v.z);
            Vt[(n4 * 4 + 3) * 68 + i] = f2tf(v.w);
        }
        __syncthreads();

#pragma unroll
        for (int kk = 0; kk < 64; kk += 8) {
            unsigned af[2][4];
#pragma unroll
            for (int mt = 0; mt < 2; mt++) {
                int r = wm + mt * 16 + gq;
                af[mt][0] = Ss[r * 68 + kk + tq];
                af[mt][1] = Ss[(r + 8) * 68 + kk + tq];
                af[mt][2] = Ss[r * 68 + kk + 4 + tq];
                af[mt][3] = Ss[(r + 8) * 68 + kk + 4 + tq];
            }
#pragma unroll
            for (int nt = 0; nt < 8; nt++) {
                int cc = wn + nt * 8 + gq;
                unsigned bf[2];
                bf[0] = Vt[cc * 68 + kk + tq];
                bf[1] = Vt[cc * 68 + kk + 4 + tq];
#pragma unroll
                for (int mt = 0; mt < 2; mt++)
                    mma_tf32(oacc[mt][nt], af[mt], bf);
            }
        }
        __syncthreads();
    }

#pragma unroll
    for (int mt = 0; mt < 2; mt++) {
        int r0 = wm + mt * 16 + gq;
#pragma unroll
        for (int nt = 0; nt < 8; nt++) {
            int cc = h * DV + dvt * 128 + wn + nt * 8 + tq * 2;
            size_t row = (size_t)(rowbase + r0);
            *(float2*)(g_o + row * VDIM + cc) =
                make_float2(oacc[mt][nt][0], oacc[mt][nt][1]);
            *(float2*)(g_o + (row + 8) * VDIM + cc) =
                make_float2(oacc[mt][nt][2], oacc[mt][nt][3]);
        }
    }
}

// ---------------------------------------------------------------------------
// RMSNorm * g_norm_w * silu(g); writes tf32-rounded o (feeds out_gemm).
// ---------------------------------------------------------------------------
__global__ __launch_bounds__(256) void gate_kernel(const float* __restrict__ gw)
{
    __shared__ float ws[8];
    const int blk = blockIdx.x;
    const int tid = threadIdx.x;
    const size_t base = (size_t)(blk >> 2) * VDIM + (size_t)(blk & 3) * DV;

    float2 o2 = *(float2*)(g_o + base + tid * 2);
    float p = o2.x * o2.x + o2.y * o2.y;
#pragma unroll
    for (int off = 16; off > 0; off >>= 1) p += __shfl_xor_sync(0xffffffffu, p, off);
    if ((tid & 31) == 0) ws[tid >> 5] = p;
    __syncthreads();
    float tot = ws[0] + ws[1] + ws[2] + ws[3] + ws[4] + ws[5] + ws[6] + ws[7];
    float rms = rsqrtf(tot * (1.0f / (float)DV) + 1e-5f);

    const int c = tid * 2;
    float2 g2 = *(const float2*)(g_g + base + c);
    float s0 = g2.x / (1.0f + expf(-g2.x));
    float s1 = g2.y / (1.0f + expf(-g2.y));
    o2.x = roundtf(o2.x * rms * gw[c] * s0);
    o2.y = roundtf(o2.y * rms * gw[c + 1] * s1);
    *(float2*)(g_o + base + c) = o2;
}

// ---------------------------------------------------------------------------
extern "C" void kernel_launch(void* const* d_in, const int* in_sizes, int n_in,
                              void* d_out, int out_size)
{
    const float* x  = (const float*)d_in[0];
    const float* Wq = (const float*)d_in[1];
    const float* Wk = (const float*)d_in[2];
    const float* Wv = (const float*)d_in[3];
    const float* Wg = (const float*)d_in[4];
    const float* Wo = (const float*)d_in[5];
    const float* gw = (const float*)d_in[6];
    float* out = (float*)d_out;

    cudaFuncSetAttribute(proj_gemm, cudaFuncAttributeMaxDynamicSharedMemorySize, GEMM_SMEM);
    cudaFuncSetAttribute(out_gemm,  cudaFuncAttributeMaxDynamicSharedMemorySize, GEMM_SMEM);
    cudaFuncSetAttribute(chunk_kv,  cudaFuncAttributeMaxDynamicSharedMemorySize, 17408 * 4);
    cudaFuncSetAttribute(chunk_out, cudaFuncAttributeMaxDynamicSharedMemorySize, POOLC_WORDS * 4);

    // Pre-round inputs to tf32 (makes mma truncation exact; enables raw cp.async)
    round_copy<<<4096, 256>>>(x,  5, 0,       1048576);  // x  -> g_x
    round_copy<<<1024, 256>>>(Wq, 6, WQ_OFF,  262144);
    round_copy<<<1024, 256>>>(Wk, 6, WK_OFF,  262144);
    round_copy<<<2048, 256>>>(Wv, 6, WV_OFF,  524288);
    round_copy<<<2048, 256>>>(Wg, 6, WG_OFF,  524288);
    round_copy<<<2048, 256>>>(Wo, 6, WO_OFF,  524288);

    // Fused projections
    dim3 gp(48, 32);
    proj_gemm<<<gp, 256, GEMM_SMEM>>>();

    rope_kernel<<<(NB * T_SEQ * NH * 128) / 256, 256>>>();

    dim3 ga(8, NCH, NB * NH);
    chunk_kv<<<ga, 256, 17408 * 4>>>();

    state_scan<<<1024, 256>>>();

    dim3 gc(4, NCH, NB * NH);
    chunk_out<<<gc, 256, POOLC_WORDS * 4>>>();

    gate_kernel<<<MROWS * NH, 256>>>(gw);

    dim3 go(8, 32);
    out_gemm<<<go, 256, GEMM_SMEM>>>(out);
}